// round 5
// baseline (speedup 1.0000x reference)
#include <cuda_runtime.h>
#include <math.h>

#define NQ  10
#define DIM 1024
#define NL  4
#define NT  256

// ---------------- compile-time GF(2) 10x10 matrix algebra ----------------
struct GF { unsigned short r[10]; };   // r[i] = row i as mask over input bits

__host__ __device__ constexpr GF gf_id() {
    GF m{}; for (int i = 0; i < 10; ++i) m.r[i] = (unsigned short)(1u << i); return m;
}
__host__ __device__ constexpr GF gf_mul(GF A, GF B) {   // (A*B) v = A (B v)
    GF C{};
    for (int i = 0; i < 10; ++i) {
        unsigned m = 0;
        for (int j = 0; j < 10; ++j) if ((A.r[i] >> j) & 1u) m ^= B.r[j];
        C.r[i] = (unsigned short)m;
    }
    return C;
}
__host__ __device__ constexpr GF gf_inv(GF A) {
    unsigned aug[10] = {};
    for (int i = 0; i < 10; ++i) aug[i] = A.r[i] | (1u << (10 + i));
    for (int c = 0; c < 10; ++c) {
        int p = c; while (((aug[p] >> c) & 1u) == 0u) ++p;
        unsigned tmp = aug[c]; aug[c] = aug[p]; aug[p] = tmp;
        for (int i = 0; i < 10; ++i) if (i != c && ((aug[i] >> c) & 1u)) aug[i] ^= aug[c];
    }
    GF R{}; for (int i = 0; i < 10; ++i) R.r[i] = (unsigned short)(aug[i] >> 10); return R;
}
__host__ __device__ constexpr unsigned short gf_col(GF A, int c) {
    unsigned m = 0; for (int i = 0; i < 10; ++i) if ((A.r[i] >> c) & 1u) m |= (1u << i);
    return (unsigned short)m;
}
// CNOT ring as linear index map: out_i = parity(v bits i..9) for i<9; out_9 = parity(v bits 0..8)
__host__ __device__ constexpr GF gf_ring() {
    GF m{};
    for (int i = 0; i < 9; ++i) m.r[i] = (unsigned short)(0x3FFu & ~((1u << i) - 1u));
    m.r[9] = 0x1FF;
    return m;
}
__host__ __device__ constexpr int gf_top(unsigned m) {
    int t = 0; for (int i = 0; i < 16; ++i) if ((m >> i) & 1u) t = i; return t;
}

struct Tables {
    unsigned short xm1[NL][5], xm2[NL][5];   // partner XOR masks (pivot-reduced)
    int blo[NL][5], bhi[NL][5];              // pivot bit positions (sorted)
    int red[NL][5];                          // 1 if m2 was replaced by m1^m2
    unsigned short r1[NL][5], r2[NL][5];     // role (row) masks for qa, qb
    unsigned short meas[NQ];                 // measurement row masks (rows of R^4)
};

__host__ __device__ constexpr Tables make_tables() {
    Tables T{};
    GF Rm = gf_ring();
    GF Rpow = gf_id();                        // R^l
    for (int l = 0; l < NL; ++l) {
        GF A = gf_inv(Rpow);                  // A_l = R^{-l}: logical -> physical
        for (int ps = 0; ps < 5; ++ps) {
            int qa = 2 * ps, qb = 2 * ps + 1;
            int pa = 9 - qa, pb = 9 - qb;
            unsigned m1 = gf_col(A, pa), m2 = gf_col(A, pb);
            T.r1[l][ps] = Rpow.r[pa];
            T.r2[l][ps] = Rpow.r[pb];
            int p1 = gf_top(m1);
            int r = (int)((m2 >> p1) & 1u);
            if (r) m2 ^= m1;                  // make pivots distinct; same coset group
            int p2 = gf_top(m2);
            T.red[l][ps] = r;
            T.xm1[l][ps] = (unsigned short)m1;
            T.xm2[l][ps] = (unsigned short)m2;
            T.blo[l][ps] = p1 < p2 ? p1 : p2;
            T.bhi[l][ps] = p1 < p2 ? p2 : p1;
        }
        Rpow = gf_mul(Rm, Rpow);
    }
    for (int q = 0; q < NQ; ++q) T.meas[q] = Rpow.r[9 - q];   // Rpow = R^4 here
    return T;
}

__device__ __forceinline__ float2 cmul(float2 a, float2 b) {
    return make_float2(a.x * b.x - a.y * b.y, a.x * b.y + a.y * b.x);
}
__device__ __forceinline__ float2 cfma(float2 w, float2 a, float2 acc) {
    acc.x = fmaf(w.x, a.x, fmaf(-w.y, a.y, acc.x));
    acc.y = fmaf(w.x, a.y, fmaf( w.y, a.x, acc.y));
    return acc;
}

__global__ __launch_bounds__(NT) void qsim_kernel(
    const float* __restrict__ inputs,   // [B, 10]
    const float* __restrict__ weights,  // [4, 10, 3]
    float* __restrict__ out)            // [B, 10]
{
    constexpr Tables TB = make_tables();

    __shared__ float2 s[DIM];                          // statevector, 8 KB
    __shared__ float2 U2[NL][NQ][4];                   // fused 2x2 per (layer,qubit)
    __shared__ __align__(16) float2 W4[NL][5][4][17];  // 4 conjugated 4x4 variants, padded
    __shared__ float  zsum[NQ];

    const int b = blockIdx.x;
    const int t = threadIdx.x;

    // init |0...0>
    #pragma unroll
    for (int k = 0; k < 4; ++k) s[t + k * NT] = make_float2(0.f, 0.f);
    if (t == 0) s[0] = make_float2(1.f, 0.f);

    // ---- phase 1: fused 2x2  U2[l][q] = RZ(w2) RY(w1) RX(w0) RY(x_q) ----
    if (t < NL * NQ) {
        const int l = t / NQ;
        const int q = t % NQ;
        float x = inputs[b * NQ + q];
        x = fminf(fmaxf(x, -3.14159265358979323846f), 3.14159265358979323846f);
        float sx, cx; sincosf(0.5f * x, &sx, &cx);
        const float* w = weights + (l * NQ + q) * 3;
        float sa, ca; sincosf(0.5f * w[0], &sa, &ca);
        float sb, cb; sincosf(0.5f * w[1], &sb, &cb);
        float sc, cc; sincosf(0.5f * w[2], &sc, &cc);
        float2 m00 = make_float2( ca * cx, -sa * sx);
        float2 m01 = make_float2(-ca * sx, -sa * cx);
        float2 m10 = make_float2( ca * sx, -sa * cx);
        float2 m11 = make_float2( ca * cx,  sa * sx);
        float2 n00 = make_float2(cb * m00.x - sb * m10.x, cb * m00.y - sb * m10.y);
        float2 n01 = make_float2(cb * m01.x - sb * m11.x, cb * m01.y - sb * m11.y);
        float2 n10 = make_float2(sb * m00.x + cb * m10.x, sb * m00.y + cb * m10.y);
        float2 n11 = make_float2(sb * m01.x + cb * m11.x, sb * m01.y + cb * m11.y);
        float2 e0 = make_float2(cc, -sc), e1 = make_float2(cc, sc);
        U2[l][q][0] = cmul(e0, n00);
        U2[l][q][1] = cmul(e0, n01);
        U2[l][q][2] = cmul(e1, n10);
        U2[l][q][3] = cmul(e1, n11);
    }
    __syncthreads();

    // ---- phase 2: all 4 conjugated variants of each fused 4x4 ----
    // group slot j=(alpha<<1)|beta; logical slot sigma(j)=L(j)^g0,
    // L(j) = identity, or (alpha^beta,beta) when m2 was pivot-reduced.
    for (int e = t; e < NL * 5 * 4 * 16; e += NT) {
        const int l  = e / 320;
        const int rm = e % 320;
        const int ps = rm / 64;
        const int g0 = (rm >> 4) & 3;
        const int c  = rm & 15;
        const int k  = c >> 2, j = c & 3;
        const int red = TB.red[l][ps];
        const int ka = (k >> 1) ^ (red ? (k & 1) : 0), kb = k & 1;
        const int ja = (j >> 1) ^ (red ? (j & 1) : 0), jb = j & 1;
        const int sk = ((ka << 1) | kb) ^ g0;
        const int sj = ((ja << 1) | jb) ^ g0;
        const int qa = 2 * ps, qb = qa + 1;
        W4[l][ps][g0][c] = cmul(U2[l][qa][((sk >> 1) << 1) | (sj >> 1)],
                                U2[l][qb][((sk &  1) << 1) | (sj &  1)]);
    }
    __syncthreads();

    // ---- main: 4 layers x 5 sweeps; CNOT rings are pure relabeling (free) ----
    #pragma unroll
    for (int l = 0; l < NL; ++l) {
        #pragma unroll
        for (int ps = 0; ps < 5; ++ps) {
            const int m1 = TB.xm1[l][ps];
            const int m2 = TB.xm2[l][ps];
            const int bl = TB.blo[l][ps], bh = TB.bhi[l][ps];
            const unsigned rr1 = TB.r1[l][ps], rr2 = TB.r2[l][ps];

            // coset representative: insert zeros at pivot bits bl < bh
            const int low  = t & ((1 << bl) - 1);
            const int mid  = (t >> bl) & ((1 << (bh - bl - 1)) - 1);
            const int high = t >> (bh - 1);
            const int p = low | (mid << (bl + 1)) | (high << (bh + 1));

            const int i0 = p, i1 = p ^ m2, i2 = p ^ m1, i3 = p ^ m1 ^ m2;
            float2 a0 = s[i0], a1 = s[i1], a2 = s[i2], a3 = s[i3];

            const int g0 = ((__popc(p & rr1) & 1) << 1) | (__popc(p & rr2) & 1);
            const float2* Wp = W4[l][ps][g0];

            float2 o0, o1, o2, o3;
            o0 = cmul(Wp[0],  a0); o0 = cfma(Wp[1],  a1, o0); o0 = cfma(Wp[2],  a2, o0); o0 = cfma(Wp[3],  a3, o0);
            o1 = cmul(Wp[4],  a0); o1 = cfma(Wp[5],  a1, o1); o1 = cfma(Wp[6],  a2, o1); o1 = cfma(Wp[7],  a3, o1);
            o2 = cmul(Wp[8],  a0); o2 = cfma(Wp[9],  a1, o2); o2 = cfma(Wp[10], a2, o2); o2 = cfma(Wp[11], a3, o2);
            o3 = cmul(Wp[12], a0); o3 = cfma(Wp[13], a1, o3); o3 = cfma(Wp[14], a2, o3); o3 = cfma(Wp[15], a3, o3);

            s[i0] = o0; s[i1] = o1; s[i2] = o2; s[i3] = o3;
            __syncthreads();
        }
    }

    // ---- measurement in relabeled basis: sign_q = parity(p & meas[q]) ----
    if (t < NQ) zsum[t] = 0.f;
    float pr[4];
    #pragma unroll
    for (int k = 0; k < 4; ++k) {
        const float2 v = s[t + k * NT];
        pr[k] = v.x * v.x + v.y * v.y;
    }
    __syncthreads();

    float z[NQ];
    #pragma unroll
    for (int q = 0; q < NQ; ++q) {
        const unsigned mq = TB.meas[q];
        float acc = 0.f;
        #pragma unroll
        for (int k = 0; k < 4; ++k) {
            const int v = t + k * NT;
            acc += (__popc(v & mq) & 1) ? -pr[k] : pr[k];
        }
        z[q] = acc;
    }
    #pragma unroll
    for (int q = 0; q < NQ; ++q) {
        float v = z[q];
        v += __shfl_xor_sync(0xFFFFFFFF, v, 16);
        v += __shfl_xor_sync(0xFFFFFFFF, v, 8);
        v += __shfl_xor_sync(0xFFFFFFFF, v, 4);
        v += __shfl_xor_sync(0xFFFFFFFF, v, 2);
        v += __shfl_xor_sync(0xFFFFFFFF, v, 1);
        if ((t & 31) == 0) atomicAdd(&zsum[q], v);
    }
    __syncthreads();
    if (t < NQ) out[b * NQ + t] = zsum[t];
}

extern "C" void kernel_launch(void* const* d_in, const int* in_sizes, int n_in,
                              void* d_out, int out_size) {
    const float* inputs  = (const float*)d_in[0];
    const float* weights = (const float*)d_in[1];
    float* out = (float*)d_out;
    const int B = in_sizes[0] / NQ;
    qsim_kernel<<<B, NT>>>(inputs, weights, out);
}

// round 6
// speedup vs baseline: 1.1592x; 1.1592x over previous
#include <cuda_runtime.h>
#include <math.h>

#define NQ  10
#define DIM 1024
#define NL  4
#define NT  256

__device__ __forceinline__ float2 cmul(float2 a, float2 b) {
    return make_float2(a.x * b.x - a.y * b.y, a.x * b.y + a.y * b.x);
}
__device__ __forceinline__ float2 cfma(float2 w, float2 a, float2 acc) {
    acc.x = fmaf(w.x, a.x, fmaf(-w.y, a.y, acc.x));
    acc.y = fmaf(w.x, a.y, fmaf( w.y, a.x, acc.y));
    return acc;
}

// One fused-4x4 sweep in the relabeled basis. ALL parameters are literal
// immediates via macro expansion (no tables in device code).
#define SWEEP(M1, M2, BLO, BHI, RR1, RR2, L, PS) do {                          \
    const int low  = t & ((1 << (BLO)) - 1);                                   \
    const int mid  = (t >> (BLO)) & ((1 << ((BHI) - (BLO) - 1)) - 1);          \
    const int high = t >> ((BHI) - 1);                                         \
    const int p = low | (mid << ((BLO) + 1)) | (high << ((BHI) + 1));          \
    const int i0 = p, i1 = p ^ (M2), i2 = p ^ (M1), i3 = p ^ (M1) ^ (M2);      \
    float2 a0 = s[i0], a1 = s[i1], a2 = s[i2], a3 = s[i3];                     \
    const int g0 = ((__popc(p & (RR1)) & 1) << 1) | (__popc(p & (RR2)) & 1);   \
    const float2* Wp = W4[L][PS][g0];                                          \
    float2 o0, o1, o2, o3;                                                     \
    o0 = cmul(Wp[0],  a0); o0 = cfma(Wp[1],  a1, o0); o0 = cfma(Wp[2],  a2, o0); o0 = cfma(Wp[3],  a3, o0); \
    o1 = cmul(Wp[4],  a0); o1 = cfma(Wp[5],  a1, o1); o1 = cfma(Wp[6],  a2, o1); o1 = cfma(Wp[7],  a3, o1); \
    o2 = cmul(Wp[8],  a0); o2 = cfma(Wp[9],  a1, o2); o2 = cfma(Wp[10], a2, o2); o2 = cfma(Wp[11], a3, o2); \
    o3 = cmul(Wp[12], a0); o3 = cfma(Wp[13], a1, o3); o3 = cfma(Wp[14], a2, o3); o3 = cfma(Wp[15], a3, o3); \
    s[i0] = o0; s[i1] = o1; s[i2] = o2; s[i3] = o3;                            \
    __syncthreads();                                                           \
} while (0)

// Layer-0 bits(0,1) sweep: p = 4t (g0 == 0), 4 consecutive amps -> float4.
#define SWEEP_F4(L, PS) do {                                                   \
    const float4* s4r = (const float4*)s;                                      \
    float4 v0 = s4r[2 * t], v1 = s4r[2 * t + 1];                               \
    float2 a0 = make_float2(v0.x, v0.y), a1 = make_float2(v0.z, v0.w);         \
    float2 a2 = make_float2(v1.x, v1.y), a3 = make_float2(v1.z, v1.w);         \
    const float2* Wp = W4[L][PS][0];                                           \
    float2 o0, o1, o2, o3;                                                     \
    o0 = cmul(Wp[0],  a0); o0 = cfma(Wp[1],  a1, o0); o0 = cfma(Wp[2],  a2, o0); o0 = cfma(Wp[3],  a3, o0); \
    o1 = cmul(Wp[4],  a0); o1 = cfma(Wp[5],  a1, o1); o1 = cfma(Wp[6],  a2, o1); o1 = cfma(Wp[7],  a3, o1); \
    o2 = cmul(Wp[8],  a0); o2 = cfma(Wp[9],  a1, o2); o2 = cfma(Wp[10], a2, o2); o2 = cfma(Wp[11], a3, o2); \
    o3 = cmul(Wp[12], a0); o3 = cfma(Wp[13], a1, o3); o3 = cfma(Wp[14], a2, o3); o3 = cfma(Wp[15], a3, o3); \
    float4* s4w = (float4*)s;                                                  \
    s4w[2 * t]     = make_float4(o0.x, o0.y, o1.x, o1.y);                      \
    s4w[2 * t + 1] = make_float4(o2.x, o2.y, o3.x, o3.y);                      \
    __syncthreads();                                                           \
} while (0)

__global__ __launch_bounds__(NT) void qsim_kernel(
    const float* __restrict__ inputs,   // [B, 10]
    const float* __restrict__ weights,  // [4, 10, 3]
    float* __restrict__ out)            // [B, 10]
{
    __shared__ float2 s[DIM];                          // statevector, 8 KB
    __shared__ float2 U2[NL][NQ][4];                   // fused 2x2 per (layer,qubit)
    __shared__ __align__(16) float2 W4[NL][5][4][17];  // 4 conjugated 4x4 variants, padded
    __shared__ float  zsum[NQ];

    const int b = blockIdx.x;
    const int t = threadIdx.x;

    // init |0...0>
    #pragma unroll
    for (int k = 0; k < 4; ++k) s[t + k * NT] = make_float2(0.f, 0.f);
    if (t == 0) s[0] = make_float2(1.f, 0.f);

    // ---- phase 1: fused 2x2  U2[l][q] = RZ(w2) RY(w1) RX(w0) RY(x_q) ----
    if (t < NL * NQ) {
        const int l = t / NQ;
        const int q = t % NQ;
        float x = inputs[b * NQ + q];
        x = fminf(fmaxf(x, -3.14159265358979323846f), 3.14159265358979323846f);
        float sx, cx; sincosf(0.5f * x, &sx, &cx);
        const float* w = weights + (l * NQ + q) * 3;
        float sa, ca; sincosf(0.5f * w[0], &sa, &ca);
        float sb, cb; sincosf(0.5f * w[1], &sb, &cb);
        float sc, cc; sincosf(0.5f * w[2], &sc, &cc);
        float2 m00 = make_float2( ca * cx, -sa * sx);
        float2 m01 = make_float2(-ca * sx, -sa * cx);
        float2 m10 = make_float2( ca * sx, -sa * cx);
        float2 m11 = make_float2( ca * cx,  sa * sx);
        float2 n00 = make_float2(cb * m00.x - sb * m10.x, cb * m00.y - sb * m10.y);
        float2 n01 = make_float2(cb * m01.x - sb * m11.x, cb * m01.y - sb * m11.y);
        float2 n10 = make_float2(sb * m00.x + cb * m10.x, sb * m00.y + cb * m10.y);
        float2 n11 = make_float2(sb * m01.x + cb * m11.x, sb * m01.y + cb * m11.y);
        float2 e0 = make_float2(cc, -sc), e1 = make_float2(cc, sc);
        U2[l][q][0] = cmul(e0, n00);
        U2[l][q][1] = cmul(e0, n01);
        U2[l][q][2] = cmul(e1, n10);
        U2[l][q][3] = cmul(e1, n11);
    }
    __syncthreads();

    // ---- phase 2: all 4 conjugated variants of each fused 4x4 ----
    // slot j=(alpha<<1)|beta; logical slot sigma(j)=L(j)^g0;
    // L = identity except the pivot-reduced pair (l==3, ps==4): (a,b)->(a^b,b).
    for (int e = t; e < NL * 5 * 4 * 16; e += NT) {
        const int l  = e / 320;
        const int rm = e % 320;
        const int ps = rm / 64;
        const int g0 = (rm >> 4) & 3;
        const int c  = rm & 15;
        const int k  = c >> 2, j = c & 3;
        const int red = (l == 3 && ps == 4) ? 1 : 0;
        const int ka = (k >> 1) ^ (red ? (k & 1) : 0), kb = k & 1;
        const int ja = (j >> 1) ^ (red ? (j & 1) : 0), jb = j & 1;
        const int sk = ((ka << 1) | kb) ^ g0;
        const int sj = ((ja << 1) | jb) ^ g0;
        const int qa = 2 * ps, qb = qa + 1;
        W4[l][ps][g0][c] = cmul(U2[l][qa][((sk >> 1) << 1) | (sj >> 1)],
                                U2[l][qb][((sk &  1) << 1) | (sj &  1)]);
    }
    __syncthreads();

    // ---- main: 20 sweeps, all constants literal; CNOT rings are relabeling ----
    // layer 0 (identity basis)
    SWEEP(0x200, 0x100, 8, 9, 0x200, 0x100, 0, 0);
    SWEEP(0x080, 0x040, 6, 7, 0x080, 0x040, 0, 1);
    SWEEP(0x020, 0x010, 4, 5, 0x020, 0x010, 0, 2);
    SWEEP(0x008, 0x004, 2, 3, 0x008, 0x004, 0, 3);
    SWEEP_F4(0, 4);                                   // masks {2,1}, p=4t, g0=0
    // layer 1 (basis R^-1; roles rows of R)
    SWEEP(0x300, 0x180, 8, 9, 0x1FF, 0x300, 1, 0);
    SWEEP(0x0C0, 0x060, 6, 7, 0x380, 0x3C0, 1, 1);
    SWEEP(0x030, 0x018, 4, 5, 0x3E0, 0x3F0, 1, 2);
    SWEEP(0x00C, 0x006, 2, 3, 0x3F8, 0x3FC, 1, 3);
    SWEEP(0x003, 0x301, 1, 9, 0x3FE, 0x3FF, 1, 4);
    // layer 2 (basis R^-2; roles rows of R^2)
    SWEEP(0x280, 0x140, 8, 9, 0x355, 0x2FF, 2, 0);
    SWEEP(0x0A0, 0x050, 6, 7, 0x17F, 0x2BF, 2, 1);
    SWEEP(0x028, 0x014, 4, 5, 0x15F, 0x2AF, 2, 2);
    SWEEP(0x00A, 0x005, 2, 3, 0x157, 0x2AB, 2, 3);
    SWEEP(0x302, 0x181, 8, 9, 0x155, 0x2AA, 2, 4);
    // layer 3 (basis R^-3; roles rows of R^3); ps4 pivot-reduced (m2^=m1)
    SWEEP(0x3C0, 0x1E0, 8, 9, 0x2CC, 0x1AA, 3, 0);
    SWEEP(0x0F0, 0x078, 6, 7, 0x0D5, 0x26A, 3, 1);
    SWEEP(0x03C, 0x01E, 4, 5, 0x335, 0x19A, 3, 2);
    SWEEP(0x00F, 0x307, 3, 9, 0x0CD, 0x266, 3, 3);
    SWEEP(0x283, 0x0C2, 7, 9, 0x333, 0x199, 3, 4);

    // ---- measurement: sign_q = parity(v & row_{9-q}(R^4)) ----
    if (t < NQ) zsum[t] = 0.f;
    float pr[4];
    #pragma unroll
    for (int k = 0; k < 4; ++k) {
        const float2 v = s[t + k * NT];
        pr[k] = v.x * v.x + v.y * v.y;
    }
    __syncthreads();

    constexpr unsigned MEAS[NQ] = {0x1BB, 0x366, 0x3B3, 0x1D9, 0x2EC,
                                   0x376, 0x3BB, 0x1DD, 0x2EE, 0x377};
    float z[NQ];
    #pragma unroll
    for (int q = 0; q < NQ; ++q) {
        const unsigned mq = MEAS[q];
        float acc = 0.f;
        #pragma unroll
        for (int k = 0; k < 4; ++k) {
            const int v = t + k * NT;
            acc += (__popc(v & mq) & 1) ? -pr[k] : pr[k];
        }
        z[q] = acc;
    }
    #pragma unroll
    for (int q = 0; q < NQ; ++q) {
        float v = z[q];
        v += __shfl_xor_sync(0xFFFFFFFF, v, 16);
        v += __shfl_xor_sync(0xFFFFFFFF, v, 8);
        v += __shfl_xor_sync(0xFFFFFFFF, v, 4);
        v += __shfl_xor_sync(0xFFFFFFFF, v, 2);
        v += __shfl_xor_sync(0xFFFFFFFF, v, 1);
        if ((t & 31) == 0) atomicAdd(&zsum[q], v);
    }
    __syncthreads();
    if (t < NQ) out[b * NQ + t] = zsum[t];
}

extern "C" void kernel_launch(void* const* d_in, const int* in_sizes, int n_in,
                              void* d_out, int out_size) {
    const float* inputs  = (const float*)d_in[0];
    const float* weights = (const float*)d_in[1];
    float* out = (float*)d_out;
    const int B = in_sizes[0] / NQ;
    qsim_kernel<<<B, NT>>>(inputs, weights, out);
}

// round 7
// speedup vs baseline: 1.3793x; 1.1899x over previous
#include <cuda_runtime.h>
#include <math.h>

#define NQ  10
#define DIM 1024
#define NL  4
#define NT  256

__device__ __forceinline__ float2 cmul(float2 a, float2 b) {
    return make_float2(a.x * b.x - a.y * b.y, a.x * b.y + a.y * b.x);
}
__device__ __forceinline__ float2 cfma(float2 w, float2 a, float2 acc) {
    acc.x = fmaf(w.x, a.x, fmaf(-w.y, a.y, acc.x));
    acc.y = fmaf(w.x, a.y, fmaf( w.y, a.x, acc.y));
    return acc;
}
// CNOT-ring as one bit permutation: suffix-XOR scan + bit9 fix (verified R2/R4)
__device__ __forceinline__ int ringperm(int v) {
    int y = v ^ (v >> 1); y ^= y >> 2; y ^= y >> 4; y ^= y >> 8;
    return (y & 0x1FF) | (((y ^ (v >> 9)) & 1) << 9);
}

#define MAT4(Wp) \
    float2 o0, o1, o2, o3;                                                      \
    o0 = cmul((Wp)[0],  a0); o0 = cfma((Wp)[1],  a1, o0); o0 = cfma((Wp)[2],  a2, o0); o0 = cfma((Wp)[3],  a3, o0); \
    o1 = cmul((Wp)[4],  a0); o1 = cfma((Wp)[5],  a1, o1); o1 = cfma((Wp)[6],  a2, o1); o1 = cfma((Wp)[7],  a3, o1); \
    o2 = cmul((Wp)[8],  a0); o2 = cfma((Wp)[9],  a1, o2); o2 = cfma((Wp)[10], a2, o2); o2 = cfma((Wp)[11], a3, o2); \
    o3 = cmul((Wp)[12], a0); o3 = cfma((Wp)[13], a1, o3); o3 = cfma((Wp)[14], a2, o3); o3 = cfma((Wp)[15], a3, o3);

// in-place sweep on `cur` for pair bits (PLb, PHb)
#define SWEEP_IP(PLb, PHb, PS) do {                                             \
    const int low  = t & ((1 << (PLb)) - 1);                                    \
    const int mid  = (t >> (PLb)) & ((1 << ((PHb) - (PLb) - 1)) - 1);           \
    const int high = t >> ((PHb) - 1);                                          \
    const int i0 = low | (mid << ((PLb) + 1)) | (high << ((PHb) + 1));          \
    const int i1 = i0 + (1 << (PLb));                                           \
    const int i2 = i0 + (1 << (PHb));                                           \
    const int i3 = i2 + (1 << (PLb));                                           \
    float2 a0 = cur[i0], a1 = cur[i1], a2 = cur[i2], a3 = cur[i3];              \
    const float2* Wp = W[l][PS];                                                \
    MAT4(Wp);                                                                   \
    cur[i0] = o0; cur[i1] = o1; cur[i2] = o2; cur[i3] = o3;                     \
    __syncthreads();                                                            \
} while (0)

// last sweep of the layer: read `cur`, write `oth` at ring-permuted addresses
#define SWEEP_PERM(PLb, PHb, PS) do {                                           \
    const int low  = t & ((1 << (PLb)) - 1);                                    \
    const int mid  = (t >> (PLb)) & ((1 << ((PHb) - (PLb) - 1)) - 1);           \
    const int high = t >> ((PHb) - 1);                                          \
    const int i0 = low | (mid << ((PLb) + 1)) | (high << ((PHb) + 1));          \
    const int i1 = i0 + (1 << (PLb));                                           \
    const int i2 = i0 + (1 << (PHb));                                           \
    const int i3 = i2 + (1 << (PLb));                                           \
    float2 a0 = cur[i0], a1 = cur[i1], a2 = cur[i2], a3 = cur[i3];              \
    const float2* Wp = W[l][PS];                                                \
    MAT4(Wp);                                                                   \
    oth[ringperm(i0)] = o0; oth[ringperm(i1)] = o1;                             \
    oth[ringperm(i2)] = o2; oth[ringperm(i3)] = o3;                             \
    __syncthreads();                                                            \
} while (0)

__global__ __launch_bounds__(NT) void qsim_kernel(
    const float* __restrict__ inputs,   // [B, 10]
    const float* __restrict__ weights,  // [4, 10, 3]
    float* __restrict__ out)            // [B, 10]
{
    // gate-bit pairings (same as R4): (PL, PH) bit positions, bit 9 = qubit 0
    // sweep order per layer: (0,1) f4, (2,8), (3,9), (4,5), (6,7)+perm
    __shared__ float2 sA[DIM], sB[DIM];               // ping-pong, 16 KB
    __shared__ float2 U2[NL][NQ][4];                  // fused 2x2 per (layer,qubit)
    __shared__ __align__(16) float2 W[NL][5][16];     // fused 4x4 per (layer,pair)
    __shared__ float  zsum[NQ];

    const int b = blockIdx.x;
    const int t = threadIdx.x;

    // init |0...0>
    #pragma unroll
    for (int k = 0; k < 4; ++k) sA[t + k * NT] = make_float2(0.f, 0.f);
    if (t == 0) sA[0] = make_float2(1.f, 0.f);

    // ---- phase 1: fused 2x2  U2[l][q] = RZ(w2) RY(w1) RX(w0) RY(x_q) ----
    if (t < NL * NQ) {
        const int l = t / NQ;
        const int q = t % NQ;
        float x = inputs[b * NQ + q];
        x = fminf(fmaxf(x, -3.14159265358979323846f), 3.14159265358979323846f);
        float sx, cx; sincosf(0.5f * x, &sx, &cx);
        const float* w = weights + (l * NQ + q) * 3;
        float sa, ca; sincosf(0.5f * w[0], &sa, &ca);
        float sb, cb; sincosf(0.5f * w[1], &sb, &cb);
        float sc, cc; sincosf(0.5f * w[2], &sc, &cc);
        float2 m00 = make_float2( ca * cx, -sa * sx);
        float2 m01 = make_float2(-ca * sx, -sa * cx);
        float2 m10 = make_float2( ca * sx, -sa * cx);
        float2 m11 = make_float2( ca * cx,  sa * sx);
        float2 n00 = make_float2(cb * m00.x - sb * m10.x, cb * m00.y - sb * m10.y);
        float2 n01 = make_float2(cb * m01.x - sb * m11.x, cb * m01.y - sb * m11.y);
        float2 n10 = make_float2(sb * m00.x + cb * m10.x, sb * m00.y + cb * m10.y);
        float2 n11 = make_float2(sb * m01.x + cb * m11.x, sb * m01.y + cb * m11.y);
        float2 e0 = make_float2(cc, -sc), e1 = make_float2(cc, sc);
        U2[l][q][0] = cmul(e0, n00);
        U2[l][q][1] = cmul(e0, n01);
        U2[l][q][2] = cmul(e1, n10);
        U2[l][q][3] = cmul(e1, n11);
    }
    __syncthreads();

    // ---- phase 2: fused 4x4  W[l][ps] = Uhi (x) Ulo  (same as R4) ----
    {
        constexpr int PLq[5] = {0, 2, 3, 4, 6};
        constexpr int PHq[5] = {1, 8, 9, 5, 7};
        #pragma unroll
        for (int ps = 0; ps < 5; ++ps) {
            const int qlo = 9 - PLq[ps], qhi = 9 - PHq[ps];
            if (t < NL * 16) {
                const int l = t >> 4;
                const int c = t & 15;
                const int i = c >> 2, j = c & 3;
                W[l][ps][c] = cmul(U2[l][qhi][((i >> 1) << 1) | (j >> 1)],
                                   U2[l][qlo][((i &  1) << 1) | (j &  1)]);
            }
        }
    }
    __syncthreads();

    // ---- main: 4 layers x 5 sweeps; ring perm folded into last sweep ----
    float2* cur = sA;
    float2* oth = sB;
    #pragma unroll
    for (int l = 0; l < NL; ++l) {
        // pair (0,1): 4 consecutive amps -> conflict-free float4, in place
        {
            const float4* r4 = (const float4*)cur;
            float4 v0 = r4[2 * t], v1 = r4[2 * t + 1];
            float2 a0 = make_float2(v0.x, v0.y), a1 = make_float2(v0.z, v0.w);
            float2 a2 = make_float2(v1.x, v1.y), a3 = make_float2(v1.z, v1.w);
            const float2* Wp = W[l][0];
            MAT4(Wp);
            float4* w4p = (float4*)cur;
            w4p[2 * t]     = make_float4(o0.x, o0.y, o1.x, o1.y);
            w4p[2 * t + 1] = make_float4(o2.x, o2.y, o3.x, o3.y);
            __syncthreads();
        }
        SWEEP_IP(2, 8, 1);
        SWEEP_IP(3, 9, 2);
        SWEEP_IP(4, 5, 3);
        SWEEP_PERM(6, 7, 4);
        float2* tmp = cur; cur = oth; oth = tmp;
    }

    // ---- measurement (canonical basis): <Z_q> via bit (9-q) signs ----
    if (t < NQ) zsum[t] = 0.f;
    float pr[4];
    #pragma unroll
    for (int k = 0; k < 4; ++k) {
        const float2 v = cur[t + k * NT];
        pr[k] = v.x * v.x + v.y * v.y;
    }
    __syncthreads();

    float z[NQ];
    #pragma unroll
    for (int q = 0; q < NQ; ++q) {
        const int pbit = 9 - q;
        float acc = 0.f;
        #pragma unroll
        for (int k = 0; k < 4; ++k) {
            const int v = t + k * NT;
            acc += ((v >> pbit) & 1) ? -pr[k] : pr[k];
        }
        z[q] = acc;
    }
    #pragma unroll
    for (int q = 0; q < NQ; ++q) {
        float v = z[q];
        v += __shfl_xor_sync(0xFFFFFFFF, v, 16);
        v += __shfl_xor_sync(0xFFFFFFFF, v, 8);
        v += __shfl_xor_sync(0xFFFFFFFF, v, 4);
        v += __shfl_xor_sync(0xFFFFFFFF, v, 2);
        v += __shfl_xor_sync(0xFFFFFFFF, v, 1);
        if ((t & 31) == 0) atomicAdd(&zsum[q], v);
    }
    __syncthreads();
    if (t < NQ) out[b * NQ + t] = zsum[t];
}

extern "C" void kernel_launch(void* const* d_in, const int* in_sizes, int n_in,
                              void* d_out, int out_size) {
    const float* inputs  = (const float*)d_in[0];
    const float* weights = (const float*)d_in[1];
    float* out = (float*)d_out;
    const int B = in_sizes[0] / NQ;
    qsim_kernel<<<B, NT>>>(inputs, weights, out);
}

// round 9
// speedup vs baseline: 1.8984x; 1.3763x over previous
#include <cuda_runtime.h>
#include <math.h>

#define NQ  10
#define DIM 1024
#define NL  4
#define NT  256

// Conflict-free storage swizzle: bit4 -> XOR 0b1101 into bits{0,2,3}, bit5 -> XOR bit1.
__device__ __forceinline__ int swz(int i) {
    return i ^ (((i >> 4) & 1) * 13) ^ (((i >> 5) & 1) * 2);
}
__device__ __forceinline__ float2 cmul(float2 a, float2 b) {
    return make_float2(a.x * b.x - a.y * b.y, a.x * b.y + a.y * b.x);
}
// CNOT-ring bit permutation (canonical basis), verified rounds 2-7.
__device__ __forceinline__ int ringperm(int v) {
    int y = v ^ (v >> 1); y ^= y >> 2; y ^= y >> 4; y ^= y >> 8;
    return (y & 0x1FF) | (((y ^ (v >> 9)) & 1) << 9);
}

// SU(2) gate [[a,b],[-conj(b),conj(a)]] applied to amplitude pair (p, q).
__device__ __forceinline__ void gp(float2 ga, float2 gb, float2& p, float2& q) {
    float2 np, nq;
    np.x =  ga.x * p.x - ga.y * p.y + gb.x * q.x - gb.y * q.y;
    np.y =  ga.x * p.y + ga.y * p.x + gb.x * q.y + gb.y * q.x;
    nq.x = -gb.x * p.x - gb.y * p.y + ga.x * q.x + ga.y * q.y;
    nq.y = -gb.x * p.y + gb.y * p.x + ga.x * q.y - ga.y * q.x;
    p = np; q = nq;
}

// In-place two-qubit sweep: amps at swizzled A0 ^ {0,C1,C2,C3}.
#define SWEEP_IP(I0, QLO, QHI, C1, C2, C3) do {                        \
    const int A0 = swz(I0);                                            \
    float2 x0 = cur[A0],        x1 = cur[A0 ^ (C1)];                   \
    float2 x2 = cur[A0 ^ (C2)], x3 = cur[A0 ^ (C3)];                   \
    const float2 la = Ua[l][QLO], lb = Ub[l][QLO];                     \
    const float2 ha = Ua[l][QHI], hb = Ub[l][QHI];                     \
    gp(la, lb, x0, x1); gp(la, lb, x2, x3);                            \
    gp(ha, hb, x0, x2); gp(ha, hb, x1, x3);                            \
    cur[A0] = x0;        cur[A0 ^ (C1)] = x1;                          \
    cur[A0 ^ (C2)] = x2; cur[A0 ^ (C3)] = x3;                          \
    __syncthreads();                                                   \
} while (0)

// Last sweep of layers 0-2: write ring-permuted into the other buffer.
// rp(i0^64)=rp(i0)^0x27F, rp(i0^128)=rp(i0)^0x2FF, rp(i0^192)=rp(i0)^0x080;
// swizzle deltas folded: 0x27F->0x270? no: swz XOR-deltas depend only on bits4,5
// of the XOR mask: mask 0x27F flips bit4,5,6... Careful: swz(a^m)=swz(a)^swz0(m)
// where swz0(m)=m^(((m>>4)&1)*13)^(((m>>5)&1)*2). swz0(0x27F)=0x27F^13^2=0x270.
// swz0(0x2FF)=0x2FF^13^2=0x2F0. swz0(0x080)=0x080.
#define SWEEP_PERM(I0, QLO, QHI) do {                                  \
    const int A0 = swz(I0);                                            \
    float2 x0 = cur[A0],        x1 = cur[A0 ^ 64];                     \
    float2 x2 = cur[A0 ^ 128],  x3 = cur[A0 ^ 192];                    \
    const float2 la = Ua[l][QLO], lb = Ub[l][QLO];                     \
    const float2 ha = Ua[l][QHI], hb = Ub[l][QHI];                     \
    gp(la, lb, x0, x1); gp(la, lb, x2, x3);                            \
    gp(ha, hb, x0, x2); gp(ha, hb, x1, x3);                            \
    const int B0 = swz(ringperm(I0));                                  \
    oth[B0] = x0;           oth[B0 ^ 0x270] = x1;                      \
    oth[B0 ^ 0x2F0] = x2;   oth[B0 ^ 0x080] = x3;                      \
    __syncthreads();                                                   \
} while (0)

__global__ __launch_bounds__(NT) void qsim_kernel(
    const float* __restrict__ inputs,   // [B, 10]
    const float* __restrict__ weights,  // [4, 10, 3]
    float* __restrict__ out)            // [B, 10]
{
    __shared__ float2 sA[DIM], sB[DIM];       // ping-pong statevector, 16 KB
    __shared__ float2 Ua[NL][NQ], Ub[NL][NQ]; // SU(2) rows (u00,u01) per (l,q)
    __shared__ float  zsum[NQ];

    const int b = blockIdx.x;
    const int t = threadIdx.x;

    // init |0...0>  (swz(0)==0)
    const int At = swz(t);
    #pragma unroll
    for (int k = 0; k < 4; ++k) sA[At ^ (k << 8)] = make_float2(0.f, 0.f);
    if (t == 0) sA[0] = make_float2(1.f, 0.f);

    // ---- phase 1: SU(2) row of fused U = RZ(w2) RY(w1) RX(w0) RY(x_q) ----
    if (t < NL * NQ) {
        const int l = t / NQ;
        const int q = t % NQ;
        float x = inputs[b * NQ + q];
        x = fminf(fmaxf(x, -3.14159265358979323846f), 3.14159265358979323846f);
        float sx, cx; sincosf(0.5f * x, &sx, &cx);
        const float* w = weights + (l * NQ + q) * 3;
        float sa, ca; sincosf(0.5f * w[0], &sa, &ca);
        float sb, cb; sincosf(0.5f * w[1], &sb, &cb);
        float sc, cc; sincosf(0.5f * w[2], &sc, &cc);
        // M1 = RX(a)*RY(x): SU(2), rows determined by (m00, m01)
        float2 m00 = make_float2( ca * cx, -sa * sx);
        float2 m01 = make_float2(-ca * sx, -sa * cx);
        // N = RY(b)*M1: n00 = cb*m00 + sb*conj(m01); n01 = cb*m01 - sb*conj(m00)
        float2 n00 = make_float2(cb * m00.x + sb * m01.x, cb * m00.y - sb * m01.y);
        float2 n01 = make_float2(cb * m01.x - sb * m00.x, cb * m01.y + sb * m00.y);
        // U = RZ(c)*N: row0 scaled by e0 = (cc, -sc)
        float2 e0 = make_float2(cc, -sc);
        Ua[l][q] = cmul(e0, n00);
        Ub[l][q] = cmul(e0, n01);
    }
    __syncthreads();

    float2* cur = sA;
    float2* oth = sB;

    // layers 0-2: 5 sweeps, ring perm folded into last sweep's write
    #pragma unroll
    for (int l = 0; l < 3; ++l) {
        SWEEP_IP(t << 2,                                   9, 8, 1, 2, 3);
        SWEEP_IP((t & 3) | (((t >> 2) & 31) << 3) | ((t >> 7) << 9),
                                                           7, 1, 4, 256, 260);
        SWEEP_IP((t & 7) | ((t >> 3) << 4),                6, 0, 8, 512, 520);
        SWEEP_IP((t & 15) | ((t >> 4) << 6),               5, 4, 0x1D, 0x22, 0x3F);
        SWEEP_PERM((t & 63) | ((t >> 6) << 8),             3, 2);
        float2* tmp = cur; cur = oth; oth = tmp;
    }
    // layer 3: all in place; final ring perm folded into measurement masks
    {
        const int l = 3;
        SWEEP_IP(t << 2,                                   9, 8, 1, 2, 3);
        SWEEP_IP((t & 3) | (((t >> 2) & 31) << 3) | ((t >> 7) << 9),
                                                           7, 1, 4, 256, 260);
        SWEEP_IP((t & 7) | ((t >> 3) << 4),                6, 0, 8, 512, 520);
        SWEEP_IP((t & 15) | ((t >> 4) << 6),               5, 4, 0x1D, 0x22, 0x3F);
        SWEEP_IP((t & 63) | ((t >> 6) << 8),               3, 2, 64, 128, 192);
    }

    // ---- measurement with ring-adjusted masks (rows of R):
    // q=0 -> bit9' = parity(bits 0-8); q>=1 -> bit(9-q)' = parity(bits (9-q)..9)
    if (t < NQ) zsum[t] = 0.f;
    float pr[4];
    #pragma unroll
    for (int k = 0; k < 4; ++k) {
        const float2 v = cur[At ^ (k << 8)];
        pr[k] = v.x * v.x + v.y * v.y;
    }
    __syncthreads();

    constexpr unsigned MEAS[NQ] = {0x1FF, 0x300, 0x380, 0x3C0, 0x3E0,
                                   0x3F0, 0x3F8, 0x3FC, 0x3FE, 0x3FF};
    float z[NQ];
    #pragma unroll
    for (int q = 0; q < NQ; ++q) {
        const unsigned mq = MEAS[q];
        float acc = 0.f;
        #pragma unroll
        for (int k = 0; k < 4; ++k) {
            const int v = t | (k << 8);
            acc += (__popc(v & mq) & 1) ? -pr[k] : pr[k];
        }
        z[q] = acc;
    }
    #pragma unroll
    for (int q = 0; q < NQ; ++q) {
        float v = z[q];
        v += __shfl_xor_sync(0xFFFFFFFF, v, 16);
        v += __shfl_xor_sync(0xFFFFFFFF, v, 8);
        v += __shfl_xor_sync(0xFFFFFFFF, v, 4);
        v += __shfl_xor_sync(0xFFFFFFFF, v, 2);
        v += __shfl_xor_sync(0xFFFFFFFF, v, 1);
        if ((t & 31) == 0) atomicAdd(&zsum[q], v);
    }
    __syncthreads();
    if (t < NQ) out[b * NQ + t] = zsum[t];
}

extern "C" void kernel_launch(void* const* d_in, const int* in_sizes, int n_in,
                              void* d_out, int out_size) {
    const float* inputs  = (const float*)d_in[0];
    const float* weights = (const float*)d_in[1];
    float* out = (float*)d_out;
    const int B = in_sizes[0] / NQ;
    qsim_kernel<<<B, NT>>>(inputs, weights, out);
}

// round 10
// speedup vs baseline: 1.9497x; 1.0270x over previous
#include <cuda_runtime.h>
#include <math.h>

#define NQ  10
#define DIM 1024
#define NL  4
#define NT  64

// Linear conflict-free swizzle: XOR bits 4,5 (and 6,7 if set) into low nibble.
__device__ __forceinline__ int swz(int i) { return i ^ ((i >> 4) & 15); }

__device__ __forceinline__ float2 cmul(float2 a, float2 b) {
    return make_float2(a.x * b.x - a.y * b.y, a.x * b.y + a.y * b.x);
}
// CNOT-ring bit permutation (linear over GF(2)), verified rounds 2-9.
__device__ __forceinline__ int ringperm(int v) {
    int y = v ^ (v >> 1); y ^= y >> 2; y ^= y >> 4; y ^= y >> 8;
    return (y & 0x1FF) | (((y ^ (v >> 9)) & 1) << 9);
}
// SU(2) gate [[a,b],[-conj(b),conj(a)]] on amplitude pair (p, q).
__device__ __forceinline__ void gp(float2 ga, float2 gb, float2& p, float2& q) {
    float2 np, nq;
    np.x =  ga.x * p.x - ga.y * p.y + gb.x * q.x - gb.y * q.y;
    np.y =  ga.x * p.y + ga.y * p.x + gb.x * q.y + gb.y * q.x;
    nq.x = -gb.x * p.x - gb.y * p.y + ga.x * q.x + ga.y * q.y;
    nq.y = -gb.x * p.y + gb.y * p.x + ga.x * q.y - ga.y * q.x;
    p = np; q = nq;
}

// Apply gate on local bit K to r[16] (8 disjoint pairs), qubit coeffs (GA,GB).
#define GATE16(K, GA, GB) do {                                          \
    const float2 _ga = (GA), _gb = (GB);                                \
    _Pragma("unroll")                                                   \
    for (int _j = 0; _j < 16; ++_j)                                     \
        if (!(_j & (1 << (K))))                                         \
            gp(_ga, _gb, r[_j], r[_j | (1 << (K))]);                    \
} while (0)

// Round A: free bits 0-3; i = t<<4 | j; loc = (t<<4) | (j ^ (t&15)).
#define ROUND_A(L) do {                                                 \
    const int _base = t << 4, _s = t & 15;                              \
    float2 r[16];                                                       \
    _Pragma("unroll")                                                   \
    for (int _j = 0; _j < 16; ++_j) r[_j] = cur[_base | (_j ^ _s)];     \
    GATE16(0, Ua[L][9], Ub[L][9]);                                      \
    GATE16(1, Ua[L][8], Ub[L][8]);                                      \
    GATE16(2, Ua[L][7], Ub[L][7]);                                      \
    GATE16(3, Ua[L][6], Ub[L][6]);                                      \
    _Pragma("unroll")                                                   \
    for (int _j = 0; _j < 16; ++_j) cur[_base | (_j ^ _s)] = r[_j];     \
    __syncthreads();                                                    \
} while (0)

// Round B: free bits 4-7; i = (t>>4)<<8 | j<<4 | (t&15); loc low4 ^= j.
#define ROUND_B(L) do {                                                 \
    const int _hb = (t >> 4) << 8, _lb = t & 15;                        \
    float2 r[16];                                                       \
    _Pragma("unroll")                                                   \
    for (int _j = 0; _j < 16; ++_j)                                     \
        r[_j] = cur[_hb | (_j << 4) | (_lb ^ _j)];                      \
    GATE16(0, Ua[L][5], Ub[L][5]);                                      \
    GATE16(1, Ua[L][4], Ub[L][4]);                                      \
    GATE16(2, Ua[L][3], Ub[L][3]);                                      \
    GATE16(3, Ua[L][2], Ub[L][2]);                                      \
    _Pragma("unroll")                                                   \
    for (int _j = 0; _j < 16; ++_j)                                     \
        cur[_hb | (_j << 4) | (_lb ^ _j)] = r[_j];                      \
    __syncthreads();                                                    \
} while (0)

// Round C loads: free bits 6-9; i = j<<6 | t; loc = tC ^ (j<<6) ^ ((j&3)<<2).
#define ROUND_C_LOAD() do {                                             \
    _Pragma("unroll")                                                   \
    for (int _j = 0; _j < 16; ++_j)                                     \
        r[_j] = cur[tC ^ (_j << 6) ^ ((_j & 3) << 2)];                  \
} while (0)

__global__ __launch_bounds__(NT) void qsim_kernel(
    const float* __restrict__ inputs,   // [B, 10]
    const float* __restrict__ weights,  // [4, 10, 3]
    float* __restrict__ out)            // [B, 10]
{
    __shared__ float2 sA[DIM], sB[DIM];       // ping-pong statevector
    __shared__ float2 Ua[NL][NQ], Ub[NL][NQ]; // SU(2) rows (u00,u01)
    __shared__ float  zsum[NQ];

    const int b = blockIdx.x;
    const int t = threadIdx.x;

    if (t < NQ) zsum[t] = 0.f;
    #pragma unroll
    for (int k = 0; k < 16; ++k) sA[t + k * NT] = make_float2(0.f, 0.f);
    if (t == 0) sA[0] = make_float2(1.f, 0.f);   // swz(0)==0

    // ---- phase 1: SU(2) row of fused U = RZ(w2) RY(w1) RX(w0) RY(x_q) ----
    if (t < NL * NQ) {
        const int l = t / NQ;
        const int q = t % NQ;
        float x = inputs[b * NQ + q];
        x = fminf(fmaxf(x, -3.14159265358979323846f), 3.14159265358979323846f);
        float sx, cx; sincosf(0.5f * x, &sx, &cx);
        const float* w = weights + (l * NQ + q) * 3;
        float sa, ca; sincosf(0.5f * w[0], &sa, &ca);
        float sb, cb; sincosf(0.5f * w[1], &sb, &cb);
        float sc, cc; sincosf(0.5f * w[2], &sc, &cc);
        float2 m00 = make_float2( ca * cx, -sa * sx);
        float2 m01 = make_float2(-ca * sx, -sa * cx);
        float2 n00 = make_float2(cb * m00.x + sb * m01.x, cb * m00.y - sb * m01.y);
        float2 n01 = make_float2(cb * m01.x - sb * m00.x, cb * m01.y + sb * m00.y);
        float2 e0 = make_float2(cc, -sc);
        Ua[l][q] = cmul(e0, n00);
        Ub[l][q] = cmul(e0, n01);
    }
    __syncthreads();

    float2* cur = sA;
    float2* oth = sB;
    const int tC = t ^ (t >> 4);                 // swz(t) for t < 64
    const int wbase = swz(ringperm(t));          // perm-write base (linear part)

    // ---- layers 0-2: rounds A, B, C(+ring perm into other buffer) ----
    #pragma unroll 1
    for (int l = 0; l < 3; ++l) {
        ROUND_A(l);
        ROUND_B(l);
        {
            float2 r[16];
            ROUND_C_LOAD();
            GATE16(2, Ua[l][1], Ub[l][1]);       // bit 8 -> qubit 1
            GATE16(3, Ua[l][0], Ub[l][0]);       // bit 9 -> qubit 0
            // scatter at swz(ringperm(i)), i = j<<6 | t; constants fold.
            #pragma unroll
            for (int j = 0; j < 16; ++j) {
                const int rpj = ((j & 1) ? 0x27F : 0) ^ ((j & 2) ? 0x2FF : 0)
                              ^ ((j & 4) ? 0x3FF : 0) ^ ((j & 8) ? 0x1FF : 0);
                const int srpj = rpj ^ ((rpj >> 4) & 15);
                oth[wbase ^ srpj] = r[j];
            }
            __syncthreads();
        }
        float2* tmp = cur; cur = oth; oth = tmp;
    }

    // ---- layer 3: A, B in smem; C + measurement straight from registers ----
    ROUND_A(3);
    ROUND_B(3);
    float2 r[16];
    ROUND_C_LOAD();
    GATE16(2, Ua[3][1], Ub[3][1]);
    GATE16(3, Ua[3][0], Ub[3][0]);

    // |amp|^2 per register; sign_q = parity(i & row_{9-q}(R)), i = j<<6 | t
    float pr[16];
    #pragma unroll
    for (int j = 0; j < 16; ++j)
        pr[j] = r[j].x * r[j].x + r[j].y * r[j].y;

    constexpr unsigned MEAS[NQ] = {0x1FF, 0x300, 0x380, 0x3C0, 0x3E0,
                                   0x3F0, 0x3F8, 0x3FC, 0x3FE, 0x3FF};
    float z[NQ];
    #pragma unroll
    for (int q = 0; q < NQ; ++q) {
        const unsigned m = MEAS[q];
        const int pt = __popc(t & m) & 1;
        float acc = 0.f;
        #pragma unroll
        for (int j = 0; j < 16; ++j) {
            const int pj = (__popc((j << 6) & m) & 1) ^ pt;  // (j<<6)&m folds
            acc += pj ? -pr[j] : pr[j];
        }
        z[q] = acc;
    }
    #pragma unroll
    for (int q = 0; q < NQ; ++q) {
        float v = z[q];
        v += __shfl_xor_sync(0xFFFFFFFF, v, 16);
        v += __shfl_xor_sync(0xFFFFFFFF, v, 8);
        v += __shfl_xor_sync(0xFFFFFFFF, v, 4);
        v += __shfl_xor_sync(0xFFFFFFFF, v, 2);
        v += __shfl_xor_sync(0xFFFFFFFF, v, 1);
        if ((t & 31) == 0) atomicAdd(&zsum[q], v);
    }
    __syncthreads();
    if (t < NQ) out[b * NQ + t] = zsum[t];
}

extern "C" void kernel_launch(void* const* d_in, const int* in_sizes, int n_in,
                              void* d_out, int out_size) {
    const float* inputs  = (const float*)d_in[0];
    const float* weights = (const float*)d_in[1];
    float* out = (float*)d_out;
    const int B = in_sizes[0] / NQ;
    qsim_kernel<<<B, NT>>>(inputs, weights, out);
}

// round 11
// speedup vs baseline: 1.9505x; 1.0004x over previous
#include <cuda_runtime.h>
#include <math.h>

#define NQ  10
#define DIM 1024
#define NL  4
#define NT  32

__device__ __forceinline__ float2 cmul(float2 a, float2 b) {
    return make_float2(a.x * b.x - a.y * b.y, a.x * b.y + a.y * b.x);
}
// CNOT-ring bit permutation (GF(2)-linear), verified rounds 2-10.
__device__ __forceinline__ int ringperm(int v) {
    int y = v ^ (v >> 1); y ^= y >> 2; y ^= y >> 4; y ^= y >> 8;
    return (y & 0x1FF) | (((y ^ (v >> 9)) & 1) << 9);
}
// Storage swizzle: XOR bits 5-8 into bits 1-4 (bit0 preserved -> float4 pairs).
__device__ __forceinline__ int swz(int i) { return i ^ (((i >> 5) << 1) & 0x1E); }
// rp(j<<5) for compile-time j: fold of basis masks rp(e5..e9).
__device__ __forceinline__ int rpb(int j) {
    int c = 0;
    if (j & 1)  c ^= 0x23F;
    if (j & 2)  c ^= 0x27F;
    if (j & 4)  c ^= 0x2FF;
    if (j & 8)  c ^= 0x3FF;
    if (j & 16) c ^= 0x1FF;
    return c;
}
// SU(2) gate [[a,b],[-conj(b),conj(a)]] on amplitude pair (p, q).
__device__ __forceinline__ void gp(float2 ga, float2 gb, float2& p, float2& q) {
    float2 np, nq;
    np.x =  ga.x * p.x - ga.y * p.y + gb.x * q.x - gb.y * q.y;
    np.y =  ga.x * p.y + ga.y * p.x + gb.x * q.y + gb.y * q.x;
    nq.x = -gb.x * p.x - gb.y * p.y + ga.x * q.x + ga.y * q.y;
    nq.y = -gb.x * p.y + gb.y * p.x + ga.x * q.y - ga.y * q.x;
    p = np; q = nq;
}
// Gate on local bit K of r[32]: 16 disjoint pairs.
#define GATE32(K, GA, GB) do {                                          \
    const float2 _ga = (GA), _gb = (GB);                                \
    _Pragma("unroll")                                                   \
    for (int _j = 0; _j < 32; ++_j)                                     \
        if (!(_j & (1 << (K))))                                         \
            gp(_ga, _gb, r[_j], r[_j | (1 << (K))]);                    \
} while (0)

__global__ __launch_bounds__(NT) void qsim_kernel(
    const float* __restrict__ inputs,   // [B, 10]
    const float* __restrict__ weights,  // [4, 10, 3]
    float* __restrict__ out)            // [B, 10]
{
    __shared__ float2 s[DIM];                  // statevector, 8 KB (in-place)
    __shared__ float2 Ua[NL][NQ], Ub[NL][NQ];  // SU(2) rows (u00,u01)

    const int b = blockIdx.x;
    const int t = threadIdx.x;

    // init |0...0>  (swz(0)==0; lane t owns float4 slots t<<4 .. t<<4|15)
    {
        float4* s4 = (float4*)s;
        #pragma unroll
        for (int m = 0; m < 16; ++m)
            s4[(t << 4) | m] = make_float4(0.f, 0.f, 0.f, 0.f);
    }
    if (t == 0) s[0] = make_float2(1.f, 0.f);

    // ---- SU(2) row of fused U = RZ(w2) RY(w1) RX(w0) RY(x_q) ----
    for (int e = t; e < NL * NQ; e += NT) {
        const int l = e / NQ;
        const int q = e % NQ;
        float x = inputs[b * NQ + q];
        x = fminf(fmaxf(x, -3.14159265358979323846f), 3.14159265358979323846f);
        float sx, cx; sincosf(0.5f * x, &sx, &cx);
        const float* w = weights + (l * NQ + q) * 3;
        float sa, ca; sincosf(0.5f * w[0], &sa, &ca);
        float sb, cb; sincosf(0.5f * w[1], &sb, &cb);
        float sc, cc; sincosf(0.5f * w[2], &sc, &cc);
        float2 m00 = make_float2( ca * cx, -sa * sx);
        float2 m01 = make_float2(-ca * sx, -sa * cx);
        float2 n00 = make_float2(cb * m00.x + sb * m01.x, cb * m00.y - sb * m01.y);
        float2 n01 = make_float2(cb * m01.x - sb * m00.x, cb * m01.y + sb * m00.y);
        float2 e0 = make_float2(cc, -sc);
        Ua[l][q] = cmul(e0, n00);
        Ub[l][q] = cmul(e0, n01);
    }
    __syncwarp();

    const int wsw = swz(ringperm(t));   // lane part of perm-scatter address
    float outv = 0.f;

    #pragma unroll 1
    for (int l = 0; l < NL; ++l) {
        // ---- round A: bits 0-4 local (qubits 9..5); lane-private region ----
        {
            float2 r[32];
            const int sh = t & 15;
            const float4* s4r = (const float4*)s;
            #pragma unroll
            for (int m = 0; m < 16; ++m) {
                const float4 v = s4r[(t << 4) | (m ^ sh)];
                r[2 * m]     = make_float2(v.x, v.y);
                r[2 * m + 1] = make_float2(v.z, v.w);
            }
            GATE32(0, Ua[l][9], Ub[l][9]);
            GATE32(1, Ua[l][8], Ub[l][8]);
            GATE32(2, Ua[l][7], Ub[l][7]);
            GATE32(3, Ua[l][6], Ub[l][6]);
            GATE32(4, Ua[l][5], Ub[l][5]);
            float4* s4w = (float4*)s;
            #pragma unroll
            for (int m = 0; m < 16; ++m)
                s4w[(t << 4) | (m ^ sh)] =
                    make_float4(r[2*m].x, r[2*m].y, r[2*m+1].x, r[2*m+1].y);
            __syncwarp();
        }
        // ---- round B: bits 5-9 local (qubits 4..0) ----
        {
            float2 r[32];
            #pragma unroll
            for (int j = 0; j < 32; ++j)
                r[j] = s[(j << 5) | (t ^ ((j & 15) << 1))];
            __syncwarp();   // whole state in registers before any store
            GATE32(0, Ua[l][4], Ub[l][4]);
            GATE32(1, Ua[l][3], Ub[l][3]);
            GATE32(2, Ua[l][2], Ub[l][2]);
            GATE32(3, Ua[l][1], Ub[l][1]);
            GATE32(4, Ua[l][0], Ub[l][0]);
            if (l < 3) {
                // in-place ring-perm scatter: addr = swz(rp(j<<5)) ^ swz(rp(t))
                #pragma unroll
                for (int j = 0; j < 32; ++j)
                    s[wsw ^ swz(rpb(j))] = r[j],
                    (void)0;
                __syncwarp();
            } else {
                // ---- measurement straight from registers ----
                float pr[32];
                #pragma unroll
                for (int j = 0; j < 32; ++j)
                    pr[j] = r[j].x * r[j].x + r[j].y * r[j].y;
                constexpr unsigned MEAS[NQ] = {0x1FF, 0x300, 0x380, 0x3C0, 0x3E0,
                                               0x3F0, 0x3F8, 0x3FC, 0x3FE, 0x3FF};
                #pragma unroll
                for (int q = 0; q < NQ; ++q) {
                    const unsigned m = MEAS[q];
                    float acc = 0.f;
                    #pragma unroll
                    for (int j = 0; j < 32; ++j)
                        acc += (__popc((j << 5) & m) & 1) ? -pr[j] : pr[j];
                    if (__popc(t & m) & 1) acc = -acc;   // factor lane sign out
                    acc += __shfl_xor_sync(0xFFFFFFFF, acc, 16);
                    acc += __shfl_xor_sync(0xFFFFFFFF, acc, 8);
                    acc += __shfl_xor_sync(0xFFFFFFFF, acc, 4);
                    acc += __shfl_xor_sync(0xFFFFFFFF, acc, 2);
                    acc += __shfl_xor_sync(0xFFFFFFFF, acc, 1);
                    if (t == q) outv = acc;
                }
            }
        }
    }

    if (t < NQ) out[b * NQ + t] = outv;
}

// BUG-FIX audit of the perm scatter line: comma-operator form is just s[..] = r[j].

extern "C" void kernel_launch(void* const* d_in, const int* in_sizes, int n_in,
                              void* d_out, int out_size) {
    const float* inputs  = (const float*)d_in[0];
    const float* weights = (const float*)d_in[1];
    float* out = (float*)d_out;
    const int B = in_sizes[0] / NQ;
    qsim_kernel<<<B, NT>>>(inputs, weights, out);
}

// round 12
// speedup vs baseline: 2.0472x; 1.0496x over previous
#include <cuda_runtime.h>
#include <math.h>

#define NQ 10
#define NL 4
#define NT 32

typedef unsigned long long u64;

// ---- packed f32x2 ops (Blackwell) ----
__device__ __forceinline__ u64 mul2(u64 a, u64 b) {
    u64 d; asm("mul.rn.f32x2 %0, %1, %2;" : "=l"(d) : "l"(a), "l"(b)); return d;
}
__device__ __forceinline__ u64 fma2(u64 a, u64 b, u64 c) {
    u64 d; asm("fma.rn.f32x2 %0, %1, %2, %3;" : "=l"(d) : "l"(a), "l"(b), "l"(c)); return d;
}
__device__ __forceinline__ u64 add2(u64 a, u64 b) {
    u64 d; asm("add.rn.f32x2 %0, %1, %2;" : "=l"(d) : "l"(a), "l"(b)); return d;
}
#define NEGM 0x8000000080000000ULL

// CNOT-ring bit permutation (GF(2)-linear), verified rounds 2-11.
__device__ __forceinline__ int ringperm(int v) {
    int y = v ^ (v >> 1); y ^= y >> 2; y ^= y >> 4; y ^= y >> 8;
    return (y & 0x1FF) | (((y ^ (v >> 9)) & 1) << 9);
}
// Storage slot map (conflict-free for rounds A, B, and perm scatter).
__device__ __forceinline__ int psw(int i) { return i ^ ((i >> 5) & 31); }

// Packed SU(2) gate on local bit K of re[32]/im[32].
// u00 = A+iB, u01 = C+iD; row1 = (-conj(u01), conj(u00)). Coeffs packed (b0,b1).
#define GATEP(Lr, Q, K) do {                                                   \
    const float* _up = &Usm[Lr][Q][0];                                         \
    const u64 A  = *(const u64*)(_up + 0),  Bc = *(const u64*)(_up + 2);       \
    const u64 C  = *(const u64*)(_up + 4),  D  = *(const u64*)(_up + 6);       \
    const u64 nB = *(const u64*)(_up + 8),  nC = *(const u64*)(_up + 10);      \
    const u64 nD = *(const u64*)(_up + 12);                                    \
    _Pragma("unroll")                                                          \
    for (int _m = 0; _m < 32; ++_m) if (!(_m & (1 << (K)))) {                  \
        const int _n = _m | (1 << (K));                                        \
        const u64 pre = re[_m], pim = im[_m], qre = re[_n], qim = im[_n];      \
        u64 ar = mul2(A, pre);  ar = fma2(nB, pim, ar);                        \
        ar = fma2(C, qre, ar);  ar = fma2(nD, qim, ar);                        \
        u64 ai = mul2(A, pim);  ai = fma2(Bc, pre, ai);                        \
        ai = fma2(C, qim, ai);  ai = fma2(D, qre, ai);                         \
        u64 br = mul2(nC, pre); br = fma2(nD, pim, br);                        \
        br = fma2(A, qre, br);  br = fma2(Bc, qim, br);                        \
        u64 bi = mul2(nC, pim); bi = fma2(D, pre, bi);                         \
        bi = fma2(A, qim, bi);  bi = fma2(nB, qre, bi);                        \
        re[_m] = ar; im[_m] = ai; re[_n] = br; im[_n] = bi;                    \
    }                                                                          \
} while (0)

__global__ __launch_bounds__(NT) void qsim_kernel(
    const float* __restrict__ inputs,   // [B, 10]
    const float* __restrict__ weights,  // [4, 10, 3]
    float* __restrict__ out)            // [B, 10]
{
    __shared__ ulonglong2 sv[1024];        // per-slot (re01, im01); 16 KB
    __shared__ float Usm[NL][NQ][14];      // A,B,C,D,-B,-C,-D packed halves

    const int blk = blockIdx.x;            // handles batches 2*blk, 2*blk+1
    const int t = threadIdx.x;

    // init |0...0> for both packed batches (slot P(0)=0)
    #pragma unroll
    for (int m = 0; m < 32; ++m) sv[(t << 5) | m] = make_ulonglong2(0ULL, 0ULL);
    if (t == 0) sv[0] = make_ulonglong2(0x3F8000003F800000ULL, 0ULL);

    // ---- phase 1: fused SU(2) row per (layer, qubit, batch-half) ----
    for (int e = t; e < NL * NQ * 2; e += NT) {
        const int half = e & 1;
        const int lq = e >> 1;
        const int l = lq / NQ, q = lq % NQ;
        const int b = 2 * blk + half;
        float x = inputs[b * NQ + q];
        x = fminf(fmaxf(x, -3.14159265358979323846f), 3.14159265358979323846f);
        float sx, cx; sincosf(0.5f * x, &sx, &cx);
        const float* w = weights + (l * NQ + q) * 3;
        float sa, ca; sincosf(0.5f * w[0], &sa, &ca);
        float sb, cb; sincosf(0.5f * w[1], &sb, &cb);
        float sc, cc; sincosf(0.5f * w[2], &sc, &cc);
        // M1 = RX(a)*RY(x); N = RY(b)*M1; U = RZ(c)*N (row 0 only, SU(2))
        const float m00x =  ca * cx, m00y = -sa * sx;
        const float m01x = -ca * sx, m01y = -sa * cx;
        const float n00x = cb * m00x + sb * m01x, n00y = cb * m00y - sb * m01y;
        const float n01x = cb * m01x - sb * m00x, n01y = cb * m01y + sb * m00y;
        const float A = cc * n00x + sc * n00y, Bv = cc * n00y - sc * n00x;
        const float C = cc * n01x + sc * n01y, Dv = cc * n01y - sc * n01x;
        float* up = &Usm[l][q][0];
        up[0 + half] = A;   up[2 + half] = Bv;
        up[4 + half] = C;   up[6 + half] = Dv;
        up[8 + half] = -Bv; up[10 + half] = -C; up[12 + half] = -Dv;
    }
    __syncwarp();

    const int wbase = psw(ringperm(t));
    u64 outp = 0;

    #pragma unroll 1
    for (int l = 0; l < NL; ++l) {
        u64 re[32], im[32];
        // ---- round A: bits 0-4 local (qubits 9..5); lane-private slots ----
        #pragma unroll
        for (int m = 0; m < 32; ++m) {
            const ulonglong2 v = sv[(t << 5) | (m ^ t)];
            re[m] = v.x; im[m] = v.y;
        }
        GATEP(l, 9, 0); GATEP(l, 8, 1); GATEP(l, 7, 2);
        GATEP(l, 6, 3); GATEP(l, 5, 4);
        #pragma unroll
        for (int m = 0; m < 32; ++m)
            sv[(t << 5) | (m ^ t)] = make_ulonglong2(re[m], im[m]);
        __syncwarp();

        // ---- round B: bits 5-9 local (qubits 4..0) ----
        #pragma unroll
        for (int j = 0; j < 32; ++j) {
            const ulonglong2 v = sv[(j << 5) | (t ^ j)];
            re[j] = v.x; im[j] = v.y;
        }
        __syncwarp();
        GATEP(l, 4, 0); GATEP(l, 3, 1); GATEP(l, 2, 2);
        GATEP(l, 1, 3); GATEP(l, 0, 4);

        if (l < 3) {
            // ring-perm scatter: slot = P(rp(j<<5)) ^ P(rp(t)); constants fold
            #pragma unroll
            for (int j = 0; j < 32; ++j) {
                int c = 0;
                if (j & 1)  c ^= 0x23F;
                if (j & 2)  c ^= 0x27F;
                if (j & 4)  c ^= 0x2FF;
                if (j & 8)  c ^= 0x3FF;
                if (j & 16) c ^= 0x1FF;
                sv[wbase ^ psw(c)] = make_ulonglong2(re[j], im[j]);
            }
            __syncwarp();
        } else {
            // ---- measurement straight from registers, packed over batches ----
            u64 pr[32];
            #pragma unroll
            for (int j = 0; j < 32; ++j)
                pr[j] = fma2(im[j], im[j], mul2(re[j], re[j]));
            constexpr unsigned MEAS[NQ] = {0x1FF, 0x300, 0x380, 0x3C0, 0x3E0,
                                           0x3F0, 0x3F8, 0x3FC, 0x3FE, 0x3FF};
            #pragma unroll
            for (int q = 0; q < NQ; ++q) {
                const unsigned m = MEAS[q];
                u64 aP = 0, aN = 0;
                #pragma unroll
                for (int j = 0; j < 32; ++j) {
                    if (__popc((j << 5) & m) & 1) aN = add2(aN, pr[j]);
                    else                          aP = add2(aP, pr[j]);
                }
                u64 d = add2(aP, aN ^ NEGM);
                if (__popc(t & m) & 1) d ^= NEGM;
                d = add2(d, __shfl_xor_sync(0xFFFFFFFFu, d, 16));
                d = add2(d, __shfl_xor_sync(0xFFFFFFFFu, d, 8));
                d = add2(d, __shfl_xor_sync(0xFFFFFFFFu, d, 4));
                d = add2(d, __shfl_xor_sync(0xFFFFFFFFu, d, 2));
                d = add2(d, __shfl_xor_sync(0xFFFFFFFFu, d, 1));
                if (t == q) outp = d;
            }
        }
    }

    if (t < NQ) {
        out[(2 * blk)     * NQ + t] = __uint_as_float((unsigned)(outp & 0xFFFFFFFFu));
        out[(2 * blk + 1) * NQ + t] = __uint_as_float((unsigned)(outp >> 32));
    }
}

extern "C" void kernel_launch(void* const* d_in, const int* in_sizes, int n_in,
                              void* d_out, int out_size) {
    const float* inputs  = (const float*)d_in[0];
    const float* weights = (const float*)d_in[1];
    float* out = (float*)d_out;
    const int B = in_sizes[0] / NQ;
    qsim_kernel<<<B / 2, NT>>>(inputs, weights, out);
}

// round 13
// speedup vs baseline: 2.2847x; 1.1160x over previous
#include <cuda_runtime.h>
#include <math.h>

#define NQ 10
#define NL 4
#define NT 64

typedef unsigned long long u64;

// ---- packed f32x2 ops (Blackwell FFMA2 via PTX) ----
__device__ __forceinline__ u64 mul2(u64 a, u64 b) {
    u64 d; asm("mul.rn.f32x2 %0, %1, %2;" : "=l"(d) : "l"(a), "l"(b)); return d;
}
__device__ __forceinline__ u64 fma2(u64 a, u64 b, u64 c) {
    u64 d; asm("fma.rn.f32x2 %0, %1, %2, %3;" : "=l"(d) : "l"(a), "l"(b), "l"(c)); return d;
}
__device__ __forceinline__ u64 add2(u64 a, u64 b) {
    u64 d; asm("add.rn.f32x2 %0, %1, %2;" : "=l"(d) : "l"(a), "l"(b)); return d;
}
#define NEGM 0x8000000080000000ULL

// CNOT-ring bit permutation (GF(2)-linear), verified rounds 2-12.
__device__ __forceinline__ int ringperm(int v) {
    int y = v ^ (v >> 1); y ^= y >> 2; y ^= y >> 4; y ^= y >> 8;
    return (y & 0x1FF) | (((y ^ (v >> 9)) & 1) << 9);
}
// Storage swizzle (R10-verified): XOR bits 4-7 into low nibble.
__device__ __forceinline__ int swz(int i) { return i ^ ((i >> 4) & 15); }

// Packed SU(2) gate on local bit K of re[16]/im[16] (8 butterflies).
// u00 = A+iB, u01 = C+iD; row1 = (-conj(u01), conj(u00)). Coeffs packed (b0,b1).
#define GATEP16(Lr, Q, K) do {                                                 \
    const float* _up = &Usm[Lr][Q][0];                                         \
    const u64 A  = *(const u64*)(_up + 0),  Bc = *(const u64*)(_up + 2);       \
    const u64 C  = *(const u64*)(_up + 4),  D  = *(const u64*)(_up + 6);       \
    const u64 nB = *(const u64*)(_up + 8),  nC = *(const u64*)(_up + 10);      \
    const u64 nD = *(const u64*)(_up + 12);                                    \
    _Pragma("unroll")                                                          \
    for (int _m = 0; _m < 16; ++_m) if (!(_m & (1 << (K)))) {                  \
        const int _n = _m | (1 << (K));                                        \
        const u64 pre = re[_m], pim = im[_m], qre = re[_n], qim = im[_n];      \
        u64 ar = mul2(A, pre);  ar = fma2(nB, pim, ar);                        \
        ar = fma2(C, qre, ar);  ar = fma2(nD, qim, ar);                        \
        u64 ai = mul2(A, pim);  ai = fma2(Bc, pre, ai);                        \
        ai = fma2(C, qim, ai);  ai = fma2(D, qre, ai);                         \
        u64 br = mul2(nC, pre); br = fma2(nD, pim, br);                        \
        br = fma2(A, qre, br);  br = fma2(Bc, qim, br);                        \
        u64 bi = mul2(nC, pim); bi = fma2(D, pre, bi);                         \
        bi = fma2(A, qim, bi);  bi = fma2(nB, qre, bi);                        \
        re[_m] = ar; im[_m] = ai; re[_n] = br; im[_n] = bi;                    \
    }                                                                          \
} while (0)

__global__ __launch_bounds__(NT) void qsim_kernel(
    const float* __restrict__ inputs,   // [B, 10]
    const float* __restrict__ weights,  // [4, 10, 3]
    float* __restrict__ out)            // [B, 10]
{
    __shared__ ulonglong2 sv[1024];        // slot = packed (re01, im01); 16 KB
    __shared__ float Usm[NL][NQ][14];      // A,B,C,D,-B,-C,-D packed halves
    __shared__ u64 zps[2][NQ];             // per-warp partial <Z_q>

    const int blk = blockIdx.x;            // batches 2*blk, 2*blk+1
    const int t = threadIdx.x;

    // init |0...0> for both packed batches (swz(0)==0; lane-private region)
    #pragma unroll
    for (int m = 0; m < 16; ++m) sv[(t << 4) | m] = make_ulonglong2(0ULL, 0ULL);
    if (t == 0) sv[0] = make_ulonglong2(0x3F8000003F800000ULL, 0ULL);

    // ---- phase 1: fused SU(2) row per (layer, qubit, batch-half) ----
    for (int e = t; e < NL * NQ * 2; e += NT) {
        const int half = e & 1;
        const int lq = e >> 1;
        const int l = lq / NQ, q = lq % NQ;
        const int b = 2 * blk + half;
        float x = inputs[b * NQ + q];
        x = fminf(fmaxf(x, -3.14159265358979323846f), 3.14159265358979323846f);
        float sx, cx; sincosf(0.5f * x, &sx, &cx);
        const float* w = weights + (l * NQ + q) * 3;
        float sa, ca; sincosf(0.5f * w[0], &sa, &ca);
        float sb, cb; sincosf(0.5f * w[1], &sb, &cb);
        float sc, cc; sincosf(0.5f * w[2], &sc, &cc);
        const float m00x =  ca * cx, m00y = -sa * sx;
        const float m01x = -ca * sx, m01y = -sa * cx;
        const float n00x = cb * m00x + sb * m01x, n00y = cb * m00y - sb * m01y;
        const float n01x = cb * m01x - sb * m00x, n01y = cb * m01y + sb * m00y;
        const float A = cc * n00x + sc * n00y, Bv = cc * n00y - sc * n00x;
        const float C = cc * n01x + sc * n01y, Dv = cc * n01y - sc * n01x;
        float* up = &Usm[l][q][0];
        up[0 + half] = A;   up[2 + half] = Bv;
        up[4 + half] = C;   up[6 + half] = Dv;
        up[8 + half] = -Bv; up[10 + half] = -C; up[12 + half] = -Dv;
    }
    __syncthreads();

    const int wbase = swz(ringperm(t));    // perm-scatter lane part (R10)
    const int tC = t ^ (t >> 4);           // swz(t) for t < 64

    #pragma unroll 1
    for (int l = 0; l < NL; ++l) {
        u64 re[16], im[16];
        // ---- round A: bits 0-3 local (qubits 9..6); lane-private slots ----
        {
            const int base = t << 4, sh = t & 15;
            #pragma unroll
            for (int j = 0; j < 16; ++j) {
                const ulonglong2 v = sv[base | (j ^ sh)];
                re[j] = v.x; im[j] = v.y;
            }
            GATEP16(l, 9, 0); GATEP16(l, 8, 1);
            GATEP16(l, 7, 2); GATEP16(l, 6, 3);
            #pragma unroll
            for (int j = 0; j < 16; ++j)
                sv[base | (j ^ sh)] = make_ulonglong2(re[j], im[j]);
            __syncthreads();
        }
        // ---- round B: bits 4-7 local (qubits 5..2) ----
        {
            const int hb = (t >> 4) << 8, lb = t & 15;
            #pragma unroll
            for (int j = 0; j < 16; ++j) {
                const ulonglong2 v = sv[hb | (j << 4) | (lb ^ j)];
                re[j] = v.x; im[j] = v.y;
            }
            GATEP16(l, 5, 0); GATEP16(l, 4, 1);
            GATEP16(l, 3, 2); GATEP16(l, 2, 3);
            #pragma unroll
            for (int j = 0; j < 16; ++j)
                sv[hb | (j << 4) | (lb ^ j)] = make_ulonglong2(re[j], im[j]);
            __syncthreads();
        }
        // ---- round C: bits 6-9 free, gates on bits 8,9 (qubits 1,0) ----
        #pragma unroll
        for (int j = 0; j < 16; ++j) {
            const ulonglong2 v = sv[tC ^ (j << 6) ^ ((j & 3) << 2)];
            re[j] = v.x; im[j] = v.y;
        }
        __syncthreads();               // full state in registers before scatter
        GATEP16(l, 1, 2); GATEP16(l, 0, 3);
        if (l < 3) {
            // in-place ring-perm scatter: addr = swz(rp(j<<6)) ^ swz(rp(t))
            #pragma unroll
            for (int j = 0; j < 16; ++j) {
                const int rpj = ((j & 1) ? 0x27F : 0) ^ ((j & 2) ? 0x2FF : 0)
                              ^ ((j & 4) ? 0x3FF : 0) ^ ((j & 8) ? 0x1FF : 0);
                const int srpj = rpj ^ ((rpj >> 4) & 15);
                sv[wbase ^ srpj] = make_ulonglong2(re[j], im[j]);
            }
            __syncthreads();
        } else {
            // ---- measurement straight from registers (ring folded in MEAS) ----
            u64 pr[16];
            #pragma unroll
            for (int j = 0; j < 16; ++j)
                pr[j] = fma2(im[j], im[j], mul2(re[j], re[j]));
            constexpr unsigned MEAS[NQ] = {0x1FF, 0x300, 0x380, 0x3C0, 0x3E0,
                                           0x3F0, 0x3F8, 0x3FC, 0x3FE, 0x3FF};
            #pragma unroll
            for (int q = 0; q < NQ; ++q) {
                const unsigned m = MEAS[q];
                u64 aP = 0, aN = 0;
                #pragma unroll
                for (int j = 0; j < 16; ++j) {
                    if (__popc((j << 6) & m) & 1) aN = add2(aN, pr[j]);
                    else                          aP = add2(aP, pr[j]);
                }
                u64 d = add2(aP, aN ^ NEGM);
                if (__popc(t & m) & 1) d ^= NEGM;
                d = add2(d, __shfl_xor_sync(0xFFFFFFFFu, d, 16));
                d = add2(d, __shfl_xor_sync(0xFFFFFFFFu, d, 8));
                d = add2(d, __shfl_xor_sync(0xFFFFFFFFu, d, 4));
                d = add2(d, __shfl_xor_sync(0xFFFFFFFFu, d, 2));
                d = add2(d, __shfl_xor_sync(0xFFFFFFFFu, d, 1));
                if ((t & 31) == 0) zps[t >> 5][q] = d;
            }
        }
    }
    __syncthreads();

    if (t < NQ) {
        const u64 d = add2(zps[0][t], zps[1][t]);
        out[(2 * blk)     * NQ + t] = __uint_as_float((unsigned)(d & 0xFFFFFFFFu));
        out[(2 * blk + 1) * NQ + t] = __uint_as_float((unsigned)(d >> 32));
    }
}

extern "C" void kernel_launch(void* const* d_in, const int* in_sizes, int n_in,
                              void* d_out, int out_size) {
    const float* inputs  = (const float*)d_in[0];
    const float* weights = (const float*)d_in[1];
    float* out = (float*)d_out;
    const int B = in_sizes[0] / NQ;
    qsim_kernel<<<B / 2, NT>>>(inputs, weights, out);
}